// round 14
// baseline (speedup 1.0000x reference)
#include <cuda_runtime.h>
#include <math.h>

#define NN 768

// ---------------- scratch ----------------
__device__ float g_q[64*NN], g_k[64*NN], g_vT[NN*64];
__device__ float g_A[128*NN], g_B[128*NN];
__device__ float g_avp[4*64*NN], g_g1[128*NN];
__device__ float g_Wp[128*64], g_bp[128];
__device__ float g_sp1[NN*NN];                 // o-split partial of score
// per-block partial stats (no atomics): [colblock 6][channel 128]
__device__ float g_s1p[6*128], g_q1p[6*128];
__device__ float g_sAp[6*128], g_qAp[6*128], g_sBp[6*128], g_qBp[6*128];
__device__ float g_sGp[6*128], g_qGp[6*128];
__device__ float g_Skp[8*NN];                  // [rowblock 8][n 768]

// ---------------- helpers ----------------
__device__ __forceinline__ float wsum(float v) {
    #pragma unroll
    for (int o = 16; o; o >>= 1) v += __shfl_xor_sync(0xffffffffu, v, o);
    return v;
}
__device__ __forceinline__ float wmax(float v) {
    #pragma unroll
    for (int o = 16; o; o >>= 1) v = fmaxf(v, __shfl_xor_sync(0xffffffffu, v, o));
    return v;
}

// wT[i*8+r] = W[(o0+r)*ldw + koff + i]
__device__ __forceinline__ void fillW8(float* wT, const float* __restrict__ W,
                                       int ldw, int o0, int koff) {
    #pragma unroll
    for (int v = threadIdx.x; v < 512; v += 256) {
        int i = v >> 3, r = v & 7;
        wT[v] = W[(o0 + r) * ldw + koff + i];
    }
}
__device__ __forceinline__ void fillW4(float* wT, const float* __restrict__ W,
                                       int ldw, int o0, int koff) {
    if (threadIdx.x < 256) {
        int i = threadIdx.x >> 2, r = threadIdx.x & 3;
        wT[threadIdx.x] = W[(o0 + r) * ldw + koff + i];
    }
}

// 8 rows x 128 cols, K=64, X streamed. acc[4].
__device__ __forceinline__ void gemm8p(const float* __restrict__ X, int c0,
                                       const float* wT, float acc[4]) {
    int c = threadIdx.x & 127, rg = threadIdx.x >> 7;
    const float* xp = X + c0 + c;
    const float* wp = wT + rg * 4;
    #pragma unroll 8
    for (int i = 0; i < 64; i++) {
        float x = __ldg(xp + i * NN);
        float4 w = *(const float4*)(wp + i * 8);
        acc[0] = fmaf(w.x, x, acc[0]); acc[1] = fmaf(w.y, x, acc[1]);
        acc[2] = fmaf(w.z, x, acc[2]); acc[3] = fmaf(w.w, x, acc[3]);
    }
}
__device__ __forceinline__ void gemm8n(const float* __restrict__ X, int c0,
                                       const float* wT, const float2* nb, float acc[4]) {
    int c = threadIdx.x & 127, rg = threadIdx.x >> 7;
    const float* xp = X + c0 + c;
    const float* wp = wT + rg * 4;
    #pragma unroll 8
    for (int i = 0; i < 64; i++) {
        float2 sb = nb[i];
        float x = fmaxf(fmaf(sb.x, __ldg(xp + i * NN), sb.y), 0.f);
        float4 w = *(const float4*)(wp + i * 8);
        acc[0] = fmaf(w.x, x, acc[0]); acc[1] = fmaf(w.y, x, acc[1]);
        acc[2] = fmaf(w.z, x, acc[2]); acc[3] = fmaf(w.w, x, acc[3]);
    }
}
template<int S>
__device__ __forceinline__ void gemm8s4(const float* __restrict__ X, int c0,
                                        const float* wT, float acc[4]) {
    int c = threadIdx.x & 127, rg = threadIdx.x >> 7;
    const float* xp = X + c0 + c;
    const float* wp = wT + rg * 4;
    #pragma unroll 4
    for (int i = 0; i < 64; i++) {
        float x = (__ldg(xp + i * NN) + __ldg(xp + i * NN + S)) +
                  (__ldg(xp + i * NN + 2 * S) + __ldg(xp + i * NN + 3 * S));
        float4 w = *(const float4*)(wp + i * 8);
        acc[0] = fmaf(w.x, x, acc[0]); acc[1] = fmaf(w.y, x, acc[1]);
        acc[2] = fmaf(w.z, x, acc[2]); acc[3] = fmaf(w.w, x, acc[3]);
    }
}
__device__ __forceinline__ void gemm4n(const float* __restrict__ X, int c0,
                                       const float* wT, const float2* nb, float acc[2]) {
    int c = threadIdx.x & 127, rg = threadIdx.x >> 7;
    const float* xp = X + c0 + c;
    const float* wp = wT + rg * 2;
    #pragma unroll 8
    for (int i = 0; i < 64; i++) {
        float2 sb = nb[i];
        float x = fmaxf(fmaf(sb.x, __ldg(xp + i * NN), sb.y), 0.f);
        float2 w = *(const float2*)(wp + i * 4);
        acc[0] = fmaf(w.x, x, acc[0]); acc[1] = fmaf(w.y, x, acc[1]);
    }
}

// Per-row (8 rows/block) sum & sumsq -> plain store to unique partial slot.
__device__ __forceinline__ void rowstats8w(const float vals[4], int base,
                                           float* sdst, float* qdst) {
    __shared__ float rs[8][4], rq[8][4];
    int wid = threadIdx.x >> 5, lane = threadIdx.x & 31, rg = threadIdx.x >> 7;
    #pragma unroll
    for (int r = 0; r < 4; r++) {
        float s = wsum(vals[r]);
        float s2 = wsum(vals[r] * vals[r]);
        if (lane == 0) { rs[rg * 4 + r][wid & 3] = s; rq[rg * 4 + r][wid & 3] = s2; }
    }
    __syncthreads();
    if (threadIdx.x < 8) {
        sdst[base + threadIdx.x] = rs[threadIdx.x][0] + rs[threadIdx.x][1] +
                                   rs[threadIdx.x][2] + rs[threadIdx.x][3];
        qdst[base + threadIdx.x] = rq[threadIdx.x][0] + rq[threadIdx.x][1] +
                                   rq[threadIdx.x][2] + rq[threadIdx.x][3];
    }
}

// ---------------- kernels ----------------

// q/k/v convs (8x128 tiles) + stage-1 stat partials + Sk partials + W', b'. Grid 161.
__global__ void k_qkv(const float* __restrict__ d1, const float* __restrict__ d2,
                      const float* __restrict__ qw, const float* __restrict__ qb,
                      const float* __restrict__ kw, const float* __restrict__ kb,
                      const float* __restrict__ vw, const float* __restrict__ vb,
                      const float* __restrict__ mhw, const float* __restrict__ mhb,
                      const float* __restrict__ cw1, const float* __restrict__ cb1,
                      const float* __restrict__ shw)
{
    __shared__ float wT[512];
    __shared__ float skred[128];
    int b = blockIdx.x, tid = threadIdx.x;
    if (b < 144) {
        int grp = b / 48, lb = b % 48;
        int rp = lb / 6, cb = lb % 6;
        int o0 = rp * 8, c0 = cb * 128;
        const float *W, *X, *Bb;
        if (grp == 0)      { W = qw; X = d1; Bb = qb; }
        else if (grp == 1) { W = kw; X = d2; Bb = kb; }
        else               { W = vw; X = d2; Bb = vb; }
        fillW8(wT, W, 64, o0, 0);
        __syncthreads();
        float acc[4] = {};
        gemm8p(X, c0, wT, acc);
        int c = tid & 127, rg = tid >> 7;
        int ob = o0 + rg * 4;
        float vals[4];
        #pragma unroll
        for (int r = 0; r < 4; r++) vals[r] = acc[r] + __ldg(Bb + ob + r);
        if (grp == 0) {
            #pragma unroll
            for (int r = 0; r < 4; r++) g_q[(ob + r) * NN + c0 + c] = vals[r];
            __syncthreads();
            rowstats8w(vals, cb * 128 + o0, g_s1p, g_q1p);
        } else if (grp == 1) {
            #pragma unroll
            for (int r = 0; r < 4; r++) g_k[(ob + r) * NN + c0 + c] = vals[r];
            float p = 0.f;
            #pragma unroll
            for (int r = 0; r < 4; r++) p = fmaf(__ldg(shw + 64 + ob + r), vals[r], p);
            if (rg == 1) skred[c] = p;
            __syncthreads();
            if (rg == 0) g_Skp[rp * NN + c0 + c] = p + skred[c];
            __syncthreads();
            rowstats8w(vals, cb * 128 + 64 + o0, g_s1p, g_q1p);
        } else {
            float4 vv;
            vv.x = vals[0]; vv.y = vals[1]; vv.z = vals[2]; vv.w = vals[3];
            *(float4*)&g_vT[(c0 + c) * 64 + ob] = vv;
        }
    } else if (b < 160) {
        int r0 = (b - 144) * 8;
        int d = tid & 63, rg = tid >> 6;
        int row = r0 + rg * 2;
        float a0 = 0.f, a1 = 0.f;
        #pragma unroll 8
        for (int i = 0; i < 64; i++) {
            float x = __ldg(mhw + i * 64 + d);
            a0 = fmaf(__ldg(cw1 + row * 128 + 64 + i), x, a0);
            a1 = fmaf(__ldg(cw1 + (row + 1) * 128 + 64 + i), x, a1);
        }
        g_Wp[row * 64 + d] = a0;
        g_Wp[(row + 1) * 64 + d] = a1;
    } else {
        if (tid < 128) {
            float s = __ldg(cb1 + tid);
            #pragma unroll 8
            for (int i = 0; i < 64; i++)
                s = fmaf(__ldg(cw1 + tid * 128 + 64 + i), __ldg(mhb + i), s);
            g_bp[tid] = s;
        }
    }
}

// A/B GEMM; stage-1 coeffs from partial sums; stage-2 stat partials. Grid 192.
__global__ void k_AB(const float* __restrict__ w1, const float* __restrict__ b1,
                     const float* __restrict__ bn1g, const float* __restrict__ bn1b)
{
    __shared__ float wT[512];
    __shared__ float2 nb[64];
    int b = blockIdx.x, tid = threadIdx.x;
    int half = b / 96, lb = b % 96;
    int o0 = (lb / 6) * 8, cb = lb % 6;
    int c0 = cb * 128;
    if (tid < 64) {
        int ch = half * 64 + tid;
        float s = 0.f, q2 = 0.f;
        #pragma unroll
        for (int j = 0; j < 6; j++) { s += g_s1p[j * 128 + ch]; q2 += g_q1p[j * 128 + ch]; }
        float m = s * (1.f / NN);
        float v = q2 * (1.f / NN) - m * m;
        float si = rsqrtf(v + 1e-3f);
        float vn = v * si * si;
        float sb = rsqrtf(vn + 1e-5f);
        float sc = si * sb * __ldg(bn1g + ch);
        nb[tid] = make_float2(sc, -m * sc + __ldg(bn1b + ch));
    }
    fillW8(wT, w1, 128, o0, half * 64);
    __syncthreads();
    float acc[4] = {};
    gemm8n(half ? g_k : g_q, c0, wT, nb, acc);
    int c = tid & 127, rg = tid >> 7;
    int ob = o0 + rg * 4;
    float vals[4];
    if (half == 0) {
        #pragma unroll
        for (int r = 0; r < 4; r++) {
            vals[r] = acc[r];
            g_A[(ob + r) * NN + c0 + c] = vals[r];
        }
    } else {
        #pragma unroll
        for (int r = 0; r < 4; r++) {
            vals[r] = acc[r] + __ldg(b1 + ob + r);
            g_B[(ob + r) * NN + c0 + c] = vals[r];
        }
    }
    __syncthreads();
    rowstats8w(vals, cb * 128 + o0, half ? g_sBp : g_sAp, half ? g_qBp : g_qAp);
}

// score_pre partials, 64x64 tiles split over o (z=0: o<64 +Sk, z=1: o>=64).
// Grid (12,12,2) x 256, 4x4 register tiles, 32-o smem chunks (17KB smem).
__global__ void __launch_bounds__(256)
k_score(const float* __restrict__ w2,
        const float* __restrict__ bn2g, const float* __restrict__ bn2b,
        float* __restrict__ out)
{
    __shared__ float As[32 * 64];
    __shared__ float Bs[32 * 64];
    __shared__ float w2s[64];
    __shared__ float Sks[64];
    __shared__ float2 scb[64];
    int tid = threadIdx.x;
    int n0 = blockIdx.y * 64, m0 = blockIdx.x * 64;
    int z = blockIdx.z;
    if (tid < 64) {
        int ch = z * 64 + tid;
        float sA = 0.f, qA = 0.f, sB = 0.f, qB = 0.f;
        #pragma unroll
        for (int j = 0; j < 6; j++) {
            sA += g_sAp[j * 128 + ch]; qA += g_qAp[j * 128 + ch];
            sB += g_sBp[j * 128 + ch]; qB += g_qBp[j * 128 + ch];
        }
        float mA = sA * (1.f / NN), mB = sB * (1.f / NN);
        float vA = qA * (1.f / NN) - mA * mA;
        float vB = qB * (1.f / NN) - mB * mB;
        float m2 = mA + mB, v2 = vA + vB;
        float si = rsqrtf(v2 + 1e-3f);
        float vn = v2 * si * si;
        float sb = rsqrtf(vn + 1e-5f);
        float sc = si * sb * __ldg(bn2g + ch);
        scb[tid] = make_float2(sc, -m2 * sc + __ldg(bn2b + ch));
        w2s[tid] = __ldg(w2 + ch);
    } else if (tid < 128) {
        int mm = tid - 64;
        float s = 0.f;
        #pragma unroll
        for (int rp = 0; rp < 8; rp++) s += g_Skp[rp * NN + m0 + mm];
        Sks[mm] = s;
    }
    __syncthreads();

    int tx = tid & 15, ty = tid >> 4;     // 4 m, 4 n per thread
    float acc[4][4] = {};
    #pragma unroll
    for (int chk = 0; chk < 2; chk++) {
        #pragma unroll
        for (int v = tid; v < 512; v += 256) {
            int o = v >> 4, j4 = (v & 15) << 2;
            int ol = chk * 32 + o;               // 0..63 within this z-half
            int og = z * 64 + ol;
            float2 sb = scb[ol];
            float4 a = *(const float4*)&g_A[og * NN + n0 + j4];
            a.x = fmaf(sb.x, a.x, sb.y); a.y = fmaf(sb.x, a.y, sb.y);
            a.z = fmaf(sb.x, a.z, sb.y); a.w = fmaf(sb.x, a.w, sb.y);
            *(float4*)&As[o * 64 + j4] = a;
            float4 bv = *(const float4*)&g_B[og * NN + m0 + j4];
            bv.x *= sb.x; bv.y *= sb.x; bv.z *= sb.x; bv.w *= sb.x;
            *(float4*)&Bs[o * 64 + j4] = bv;
        }
        __syncthreads();
        #pragma unroll 2
        for (int o = 0; o < 32; o++) {
            float4 a = *(const float4*)&As[o * 64 + ty * 4];
            float4 bv = *(const float4*)&Bs[o * 64 + tx * 4];
            float w = w2s[chk * 32 + o];
            #pragma unroll
            for (int rn = 0; rn < 4; rn++) {
                float av = (rn == 0) ? a.x : (rn == 1) ? a.y : (rn == 2) ? a.z : a.w;
                acc[rn][0] = fmaf(w, fmaxf(av + bv.x, 0.f), acc[rn][0]);
                acc[rn][1] = fmaf(w, fmaxf(av + bv.y, 0.f), acc[rn][1]);
                acc[rn][2] = fmaf(w, fmaxf(av + bv.z, 0.f), acc[rn][2]);
                acc[rn][3] = fmaf(w, fmaxf(av + bv.w, 0.f), acc[rn][3]);
            }
        }
        __syncthreads();
    }
    float* dst = z ? g_sp1 : out;
    #pragma unroll
    for (int rn = 0; rn < 4; rn++) {
        int n = n0 + ty * 4 + rn;
        float4 o4;
        if (z == 0) {
            o4.x = acc[rn][0] + Sks[tx * 4 + 0];
            o4.y = acc[rn][1] + Sks[tx * 4 + 1];
            o4.z = acc[rn][2] + Sks[tx * 4 + 2];
            o4.w = acc[rn][3] + Sks[tx * 4 + 3];
        } else {
            o4.x = acc[rn][0]; o4.y = acc[rn][1];
            o4.z = acc[rn][2]; o4.w = acc[rn][3];
        }
        *(float4*)&dst[n * NN + m0 + tx * 4] = o4;
    }
}

// softmax over (score + partial1), in place. 4 rows/block, 2 warps/row. Grid 192 x 256.
__global__ void k_softmax(float* __restrict__ score)
{
    __shared__ float mred[4][2], sred[4][2];
    int tid = threadIdx.x;
    int wid = tid >> 5, lane = tid & 31;
    int row = blockIdx.x * 4 + (wid >> 1);
    int hf = wid & 1;
    float* p = score + row * NN + hf * 384;
    const float* p1 = g_sp1 + row * NN + hf * 384;
    float v[12];
    float mx = -1e30f;
    #pragma unroll
    for (int i = 0; i < 12; i++) {
        v[i] = p[lane + i * 32] + __ldg(p1 + lane + i * 32);
        mx = fmaxf(mx, v[i]);
    }
    mx = wmax(mx);
    if (lane == 0) mred[wid >> 1][hf] = mx;
    __syncthreads();
    mx = fmaxf(mred[wid >> 1][0], mred[wid >> 1][1]);
    float s = 0.f;
    #pragma unroll
    for (int i = 0; i < 12; i++) { v[i] = __expf(v[i] - mx); s += v[i]; }
    s = wsum(s);
    if (lane == 0) sred[wid >> 1][hf] = s;
    __syncthreads();
    float inv = 1.f / (sred[wid >> 1][0] + sred[wid >> 1][1]);
    #pragma unroll
    for (int i = 0; i < 12; i++) p[lane + i * 32] = v[i] * inv;
}

// av partials: 48 n-tiles x 4 k-splits = 192 x 256.
__global__ void k_av(const float* __restrict__ score)
{
    int bx = blockIdx.x;
    int nt = bx % 48, ks = bx / 48;
    int n0 = nt * 16;
    int tid = threadIdx.x;
    __shared__ float Vs[64][64];
    __shared__ float Ps[16][64];
    int d0  = (tid & 31) * 2;
    int nl0 = (tid >> 5) * 2;
    float a00 = 0.f, a01 = 0.f, a10 = 0.f, a11 = 0.f;
    for (int c = 0; c < 3; c++) {
        int mb = ks * 192 + c * 64;
        for (int idx = tid; idx < 64 * 64; idx += 256)
            Vs[idx >> 6][idx & 63] = g_vT[(mb + (idx >> 6)) * 64 + (idx & 63)];
        for (int idx = tid; idx < 16 * 64; idx += 256)
            Ps[idx >> 6][idx & 63] = score[(n0 + (idx >> 6)) * NN + mb + (idx & 63)];
        __syncthreads();
        #pragma unroll 4
        for (int m = 0; m < 64; m++) {
            float2 vv = *(const float2*)&Vs[m][d0];
            float p0 = Ps[nl0][m], p1 = Ps[nl0 + 1][m];
            a00 = fmaf(p0, vv.x, a00); a01 = fmaf(p0, vv.y, a01);
            a10 = fmaf(p1, vv.x, a10); a11 = fmaf(p1, vv.y, a11);
        }
        __syncthreads();
    }
    float* dst = g_avp + ks * (64 * NN);
    dst[d0 * NN + n0 + nl0]           = a00;
    dst[(d0 + 1) * NN + n0 + nl0]     = a01;
    dst[d0 * NN + n0 + nl0 + 1]       = a10;
    dst[(d0 + 1) * NN + n0 + nl0 + 1] = a11;
}

// g1 = cw1[:,:64]@desc1 + W'@(sum of 4 av partials) + b'; bn1d stat partials. Grid 96.
__global__ void k_g1(const float* __restrict__ cw1, const float* __restrict__ desc1)
{
    __shared__ float wT[512];
    int b = blockIdx.x, tid = threadIdx.x;
    int o0 = (b / 6) * 8, cb = b % 6;
    int c0 = cb * 128;
    float acc[4] = {};
    fillW8(wT, cw1, 128, o0, 0);
    __syncthreads();
    gemm8p(desc1, c0, wT, acc);
    __syncthreads();
    fillW8(wT, g_Wp, 64, o0, 0);
    __syncthreads();
    gemm8s4<64 * NN>(g_avp, c0, wT, acc);
    int c = tid & 127, rg = tid >> 7;
    int ob = o0 + rg * 4;
    float vals[4];
    #pragma unroll
    for (int r = 0; r < 4; r++) {
        vals[r] = acc[r] + g_bp[ob + r];
        g_g1[(ob + r) * NN + c0 + c] = vals[r];
    }
    __syncthreads();
    rowstats8w(vals, cb * 128 + o0, g_sGp, g_qGp);
}

// out_desc = desc1 + cw2 @ relu(norm(g1)) + cb2. 4-row tiles, Grid 96 x 256.
__global__ void k_final(const float* __restrict__ cw2, const float* __restrict__ cb2,
                        const float* __restrict__ cbg, const float* __restrict__ cbb,
                        const float* __restrict__ desc1, float* __restrict__ out)
{
    __shared__ float wT[256];
    __shared__ float2 ncf[128];
    int b = blockIdx.x, tid = threadIdx.x;
    int o0 = (b / 6) * 4, c0 = (b % 6) * 128;
    if (tid < 128) {
        float s = 0.f, q2 = 0.f;
        #pragma unroll
        for (int j = 0; j < 6; j++) { s += g_sGp[j * 128 + tid]; q2 += g_qGp[j * 128 + tid]; }
        float m = s * (1.f / NN);
        float v = q2 * (1.f / NN) - m * m;
        float sc = rsqrtf(v + 1e-5f) * __ldg(cbg + tid);
        ncf[tid] = make_float2(sc, -m * sc + __ldg(cbb + tid));
    }
    float acc[2] = {};
    fillW4(wT, cw2, 128, o0, 0);
    __syncthreads();
    gemm4n(g_g1, c0, wT, ncf, acc);
    __syncthreads();
    fillW4(wT, cw2, 128, o0, 64);
    __syncthreads();
    gemm4n(g_g1 + 64 * NN, c0, wT, ncf + 64, acc);
    int c = tid & 127, rg = tid >> 7;
    int ob = o0 + rg * 2;
    #pragma unroll
    for (int r = 0; r < 2; r++)
        out[(ob + r) * NN + c0 + c] =
            acc[r] + __ldg(cb2 + ob + r) + __ldg(desc1 + (ob + r) * NN + c0 + c);
}

// ---------------- launch ----------------
extern "C" void kernel_launch(void* const* d_in, const int* in_sizes, int n_in,
                              void* d_out, int out_size)
{
    const float* desc1 = (const float*)d_in[0];
    const float* desc2 = (const float*)d_in[1];
    const float* qw  = (const float*)d_in[2];  const float* qb  = (const float*)d_in[3];
    const float* kw  = (const float*)d_in[4];  const float* kb  = (const float*)d_in[5];
    const float* vw  = (const float*)d_in[6];  const float* vb  = (const float*)d_in[7];
    const float* mhw = (const float*)d_in[8];  const float* mhb = (const float*)d_in[9];
    const float* cw1 = (const float*)d_in[10]; const float* cb1 = (const float*)d_in[11];
    const float* cbg = (const float*)d_in[12]; const float* cbb = (const float*)d_in[13];
    const float* cw2 = (const float*)d_in[14]; const float* cb2 = (const float*)d_in[15];
    const float* shw = (const float*)d_in[16];
    const float* bn1g = (const float*)d_in[18]; const float* bn1b = (const float*)d_in[19];
    const float* sw1 = (const float*)d_in[20]; const float* sb1 = (const float*)d_in[21];
    const float* bn2g = (const float*)d_in[22]; const float* bn2b = (const float*)d_in[23];
    const float* sw2 = (const float*)d_in[24];

    float* out = (float*)d_out;
    float* out_desc  = out;
    float* out_score = out + 64 * NN;

    k_qkv<<<161, 256>>>(desc1, desc2, qw, qb, kw, kb, vw, vb, mhw, mhb, cw1, cb1, shw);
    k_AB<<<192, 256>>>(sw1, sb1, bn1g, bn1b);
    k_score<<<dim3(12, 12, 2), 256>>>(sw2, bn2g, bn2b, out_score);
    k_softmax<<<192, 256>>>(out_score);
    k_av<<<192, 256>>>(out_score);
    k_g1<<<96, 256>>>(cw1, desc1);
    k_final<<<96, 256>>>(cw2, cb2, cbg, cbb, desc1, out_desc);
}

// round 15
// speedup vs baseline: 1.1329x; 1.1329x over previous
#include <cuda_runtime.h>
#include <math.h>

#define NN 768
#define GB 288

// ---------------- scratch ----------------
__device__ float g_q[64*NN], g_k[64*NN], g_vT[NN*64];
__device__ float g_A[128*NN], g_B[128*NN];
__device__ float g_avp[4*64*NN], g_g1[128*NN];
__device__ float g_Wp[128*64], g_bp[128];
__device__ float g_sp1[NN*NN];
__device__ float g_s1p[6*128], g_q1p[6*128];
__device__ float g_sAp[6*128], g_qAp[6*128], g_sBp[6*128], g_qBp[6*128];
__device__ float g_sGp[6*128], g_qGp[6*128];
__device__ float g_Skp[8*NN];
__device__ int g_bar_count;
__device__ volatile int g_bar_gen;

// ---------------- grid barrier (288 blocks co-resident at 2/SM) ----------------
__device__ __forceinline__ void gsync() {
    __threadfence();
    __syncthreads();
    if (threadIdx.x == 0) {
        int gen = g_bar_gen;
        if (atomicAdd(&g_bar_count, 1) == GB - 1) {
            g_bar_count = 0;
            __threadfence();
            g_bar_gen = gen + 1;
        } else {
            while (g_bar_gen == gen) __nanosleep(64);
        }
    }
    __syncthreads();
}

// ---------------- helpers ----------------
__device__ __forceinline__ float wsum(float v) {
    #pragma unroll
    for (int o = 16; o; o >>= 1) v += __shfl_xor_sync(0xffffffffu, v, o);
    return v;
}
__device__ __forceinline__ float wmax(float v) {
    #pragma unroll
    for (int o = 16; o; o >>= 1) v = fmaxf(v, __shfl_xor_sync(0xffffffffu, v, o));
    return v;
}

__device__ __forceinline__ void fillW8(float* wT, const float* __restrict__ W,
                                       int ldw, int o0, int koff) {
    #pragma unroll
    for (int v = threadIdx.x; v < 512; v += 256) {
        int i = v >> 3, r = v & 7;
        wT[v] = W[(o0 + r) * ldw + koff + i];
    }
}
__device__ __forceinline__ void fillW4(float* wT, const float* __restrict__ W,
                                       int ldw, int o0, int koff) {
    if (threadIdx.x < 256) {
        int i = threadIdx.x >> 2, r = threadIdx.x & 3;
        wT[threadIdx.x] = W[(o0 + r) * ldw + koff + i];
    }
}

__device__ __forceinline__ void gemm8p(const float* __restrict__ X, int c0,
                                       const float* wT, float acc[4]) {
    int c = threadIdx.x & 127, rg = threadIdx.x >> 7;
    const float* xp = X + c0 + c;
    const float* wp = wT + rg * 4;
    #pragma unroll 8
    for (int i = 0; i < 64; i++) {
        float x = __ldg(xp + i * NN);
        float4 w = *(const float4*)(wp + i * 8);
        acc[0] = fmaf(w.x, x, acc[0]); acc[1] = fmaf(w.y, x, acc[1]);
        acc[2] = fmaf(w.z, x, acc[2]); acc[3] = fmaf(w.w, x, acc[3]);
    }
}
__device__ __forceinline__ void gemm8n(const float* __restrict__ X, int c0,
                                       const float* wT, const float2* nb, float acc[4]) {
    int c = threadIdx.x & 127, rg = threadIdx.x >> 7;
    const float* xp = X + c0 + c;
    const float* wp = wT + rg * 4;
    #pragma unroll 8
    for (int i = 0; i < 64; i++) {
        float2 sb = nb[i];
        float x = fmaxf(fmaf(sb.x, __ldg(xp + i * NN), sb.y), 0.f);
        float4 w = *(const float4*)(wp + i * 8);
        acc[0] = fmaf(w.x, x, acc[0]); acc[1] = fmaf(w.y, x, acc[1]);
        acc[2] = fmaf(w.z, x, acc[2]); acc[3] = fmaf(w.w, x, acc[3]);
    }
}
template<int S>
__device__ __forceinline__ void gemm8s4(const float* __restrict__ X, int c0,
                                        const float* wT, float acc[4]) {
    int c = threadIdx.x & 127, rg = threadIdx.x >> 7;
    const float* xp = X + c0 + c;
    const float* wp = wT + rg * 4;
    #pragma unroll 4
    for (int i = 0; i < 64; i++) {
        float x = (__ldg(xp + i * NN) + __ldg(xp + i * NN + S)) +
                  (__ldg(xp + i * NN + 2 * S) + __ldg(xp + i * NN + 3 * S));
        float4 w = *(const float4*)(wp + i * 8);
        acc[0] = fmaf(w.x, x, acc[0]); acc[1] = fmaf(w.y, x, acc[1]);
        acc[2] = fmaf(w.z, x, acc[2]); acc[3] = fmaf(w.w, x, acc[3]);
    }
}
__device__ __forceinline__ void gemm4n(const float* __restrict__ X, int c0,
                                       const float* wT, const float2* nb, float acc[2]) {
    int c = threadIdx.x & 127, rg = threadIdx.x >> 7;
    const float* xp = X + c0 + c;
    const float* wp = wT + rg * 2;
    #pragma unroll 8
    for (int i = 0; i < 64; i++) {
        float2 sb = nb[i];
        float x = fmaxf(fmaf(sb.x, __ldg(xp + i * NN), sb.y), 0.f);
        float2 w = *(const float2*)(wp + i * 4);
        acc[0] = fmaf(w.x, x, acc[0]); acc[1] = fmaf(w.y, x, acc[1]);
    }
}

__device__ __forceinline__ void rowstats8w(const float vals[4], int base,
                                           float* sdst, float* qdst) {
    __shared__ float rs[8][4], rq[8][4];
    int wid = threadIdx.x >> 5, lane = threadIdx.x & 31, rg = threadIdx.x >> 7;
    #pragma unroll
    for (int r = 0; r < 4; r++) {
        float s = wsum(vals[r]);
        float s2 = wsum(vals[r] * vals[r]);
        if (lane == 0) { rs[rg * 4 + r][wid & 3] = s; rq[rg * 4 + r][wid & 3] = s2; }
    }
    __syncthreads();
    if (threadIdx.x < 8) {
        sdst[base + threadIdx.x] = rs[threadIdx.x][0] + rs[threadIdx.x][1] +
                                   rs[threadIdx.x][2] + rs[threadIdx.x][3];
        qdst[base + threadIdx.x] = rq[threadIdx.x][0] + rq[threadIdx.x][1] +
                                   rq[threadIdx.x][2] + rq[threadIdx.x][3];
    }
}

// ---------------- fused persistent kernel ----------------
__global__ void __launch_bounds__(256, 2)
k_fused(const float* __restrict__ d1, const float* __restrict__ d2,
        const float* __restrict__ qw, const float* __restrict__ qb,
        const float* __restrict__ kw, const float* __restrict__ kb,
        const float* __restrict__ vw, const float* __restrict__ vbias,
        const float* __restrict__ mhw, const float* __restrict__ mhb,
        const float* __restrict__ cw1, const float* __restrict__ cb1,
        const float* __restrict__ cbg, const float* __restrict__ cbb,
        const float* __restrict__ cw2, const float* __restrict__ cb2,
        const float* __restrict__ shw,
        const float* __restrict__ bn1g, const float* __restrict__ bn1b,
        const float* __restrict__ sw1, const float* __restrict__ sb1,
        const float* __restrict__ bn2g, const float* __restrict__ bn2b,
        const float* __restrict__ sw2,
        float* __restrict__ out_desc, float* __restrict__ out_score)
{
    __shared__ union {
        struct { float wT[512]; float2 nb[64]; float skred[128]; } g;
        struct { float As[2048]; float Bs[2048]; float w2s[64]; float Sks[64];
                 float2 scb[64]; } sc;
        struct { float mred[4][2]; float sred[4][2]; } sm;
        struct { float Vs[4096]; float Ps[1024]; } av;
        struct { float wT4[256]; float2 ncf[128]; } f;
    } u;

    int vb = blockIdx.x, tid = threadIdx.x;

    // ===== S1: qkv convs + stage-1 stat partials + Sk partials + W', b' =====
    if (vb < 144) {
        int grp = vb / 48, lb = vb % 48;
        int rp = lb / 6, cb = lb % 6;
        int o0 = rp * 8, c0 = cb * 128;
        const float *W, *X, *Bb;
        if (grp == 0)      { W = qw; X = d1; Bb = qb; }
        else if (grp == 1) { W = kw; X = d2; Bb = kb; }
        else               { W = vw; X = d2; Bb = vbias; }
        fillW8(u.g.wT, W, 64, o0, 0);
        __syncthreads();
        float acc[4] = {};
        gemm8p(X, c0, u.g.wT, acc);
        int c = tid & 127, rg = tid >> 7;
        int ob = o0 + rg * 4;
        float vals[4];
        #pragma unroll
        for (int r = 0; r < 4; r++) vals[r] = acc[r] + __ldg(Bb + ob + r);
        if (grp == 0) {
            #pragma unroll
            for (int r = 0; r < 4; r++) g_q[(ob + r) * NN + c0 + c] = vals[r];
            __syncthreads();
            rowstats8w(vals, cb * 128 + o0, g_s1p, g_q1p);
        } else if (grp == 1) {
            #pragma unroll
            for (int r = 0; r < 4; r++) g_k[(ob + r) * NN + c0 + c] = vals[r];
            float p = 0.f;
            #pragma unroll
            for (int r = 0; r < 4; r++) p = fmaf(__ldg(shw + 64 + ob + r), vals[r], p);
            if (rg == 1) u.g.skred[c] = p;
            __syncthreads();
            if (rg == 0) g_Skp[rp * NN + c0 + c] = p + u.g.skred[c];
            __syncthreads();
            rowstats8w(vals, cb * 128 + 64 + o0, g_s1p, g_q1p);
        } else {
            float4 vv;
            vv.x = vals[0]; vv.y = vals[1]; vv.z = vals[2]; vv.w = vals[3];
            *(float4*)&g_vT[(c0 + c) * 64 + ob] = vv;
        }
    } else if (vb < 160) {
        int r0 = (vb - 144) * 8;
        int d = tid & 63, rg = tid >> 6;
        int row = r0 + rg * 2;
        float a0 = 0.f, a1 = 0.f;
        #pragma unroll 8
        for (int i = 0; i < 64; i++) {
            float x = __ldg(mhw + i * 64 + d);
            a0 = fmaf(__ldg(cw1 + row * 128 + 64 + i), x, a0);
            a1 = fmaf(__ldg(cw1 + (row + 1) * 128 + 64 + i), x, a1);
        }
        g_Wp[row * 64 + d] = a0;
        g_Wp[(row + 1) * 64 + d] = a1;
    } else if (vb == 160) {
        if (tid < 128) {
            float s = __ldg(cb1 + tid);
            #pragma unroll 8
            for (int i = 0; i < 64; i++)
                s = fmaf(__ldg(cw1 + tid * 128 + 64 + i), __ldg(mhb + i), s);
            g_bp[tid] = s;
        }
    }
    gsync();

    // ===== S2: A/B GEMM; stage-1 coeffs from partials; stage-2 stat partials =====
    if (vb < 192) {
        int half = vb / 96, lb = vb % 96;
        int o0 = (lb / 6) * 8, cb = lb % 6;
        int c0 = cb * 128;
        if (tid < 64) {
            int ch = half * 64 + tid;
            float s = 0.f, q2 = 0.f;
            #pragma unroll
            for (int j = 0; j < 6; j++) { s += g_s1p[j * 128 + ch]; q2 += g_q1p[j * 128 + ch]; }
            float m = s * (1.f / NN);
            float v = q2 * (1.f / NN) - m * m;
            float si = rsqrtf(v + 1e-3f);
            float vn = v * si * si;
            float sb = rsqrtf(vn + 1e-5f);
            float sc = si * sb * __ldg(bn1g + ch);
            u.g.nb[tid] = make_float2(sc, -m * sc + __ldg(bn1b + ch));
        }
        fillW8(u.g.wT, sw1, 128, o0, half * 64);
        __syncthreads();
        float acc[4] = {};
        gemm8n(half ? g_k : g_q, c0, u.g.wT, u.g.nb, acc);
        int c = tid & 127, rg = tid >> 7;
        int ob = o0 + rg * 4;
        float vals[4];
        if (half == 0) {
            #pragma unroll
            for (int r = 0; r < 4; r++) {
                vals[r] = acc[r];
                g_A[(ob + r) * NN + c0 + c] = vals[r];
            }
        } else {
            #pragma unroll
            for (int r = 0; r < 4; r++) {
                vals[r] = acc[r] + __ldg(sb1 + ob + r);
                g_B[(ob + r) * NN + c0 + c] = vals[r];
            }
        }
        __syncthreads();
        rowstats8w(vals, cb * 128 + o0, half ? g_sBp : g_sAp, half ? g_qBp : g_qAp);
    }
    gsync();

    // ===== S3: score_pre partials, 64x64 tiles, o-split (288 tiles) =====
    {
        int z = vb / 144, rem = vb % 144;
        int n0 = (rem / 12) * 64, m0 = (rem % 12) * 64;
        if (tid < 64) {
            int ch = z * 64 + tid;
            float sA = 0.f, qA = 0.f, sB = 0.f, qB = 0.f;
            #pragma unroll
            for (int j = 0; j < 6; j++) {
                sA += g_sAp[j * 128 + ch]; qA += g_qAp[j * 128 + ch];
                sB += g_sBp[j * 128 + ch]; qB += g_qBp[j * 128 + ch];
            }
            float mA = sA * (1.f / NN), mB = sB * (1.f / NN);
            float vA = qA * (1.f / NN) - mA * mA;
            float vB = qB * (1.f / NN) - mB * mB;
            float m2 = mA + mB, v2 = vA + vB;
            float si = rsqrtf(v2 + 1e-3f);
            float vn = v2 * si * si;
            float sb = rsqrtf(vn + 1e-5f);
            float sc = si * sb * __ldg(bn2g + ch);
            u.sc.scb[tid] = make_float2(sc, -m2 * sc + __ldg(bn2b + ch));
            u.sc.w2s[tid] = __ldg(sw2 + ch);
        } else if (tid < 128) {
            int mm = tid - 64;
            float s = 0.f;
            #pragma unroll
            for (int rp = 0; rp < 8; rp++) s += g_Skp[rp * NN + m0 + mm];
            u.sc.Sks[mm] = s;
        }
        __syncthreads();

        int tx = tid & 15, ty = tid >> 4;
        float acc[4][4] = {};
        #pragma unroll
        for (int chk = 0; chk < 2; chk++) {
            #pragma unroll
            for (int v = tid; v < 512; v += 256) {
                int o = v >> 4, j4 = (v & 15) << 2;
                int ol = chk * 32 + o;
                int og = z * 64 + ol;
                float2 sb = u.sc.scb[ol];
                float4 a = *(const float4*)&g_A[og * NN + n0 + j4];
                a.x = fmaf(sb.x, a.x, sb.y); a.y = fmaf(sb.x, a.y, sb.y);
                a.z = fmaf(sb.x, a.z, sb.y); a.w = fmaf(sb.x, a.w, sb.y);
                *(float4*)&u.sc.As[o * 64 + j4] = a;
                float4 bv = *(const float4*)&g_B[og * NN + m0 + j4];
                bv.x *= sb.x; bv.y *= sb.x; bv.z *= sb.x; bv.w *= sb.x;
                *(float4*)&u.sc.Bs[o * 64 + j4] = bv;
            }
            __syncthreads();
            #pragma unroll 2
            for (int o = 0; o < 32; o++) {
                float4 a = *(const float4*)&u.sc.As[o * 64 + ty * 4];
                float4 bv = *(const float4*)&u.sc.Bs[o * 64 + tx * 4];
                float w = u.sc.w2s[chk * 32 + o];
                #pragma unroll
                for (int rn = 0; rn < 4; rn++) {
                    float av = (rn == 0) ? a.x : (rn == 1) ? a.y : (rn == 2) ? a.z : a.w;
                    acc[rn][0] = fmaf(w, fmaxf(av + bv.x, 0.f), acc[rn][0]);
                    acc[rn][1] = fmaf(w, fmaxf(av + bv.y, 0.f), acc[rn][1]);
                    acc[rn][2] = fmaf(w, fmaxf(av + bv.z, 0.f), acc[rn][2]);
                    acc[rn][3] = fmaf(w, fmaxf(av + bv.w, 0.f), acc[rn][3]);
                }
            }
            __syncthreads();
        }
        float* dst = z ? g_sp1 : out_score;
        #pragma unroll
        for (int rn = 0; rn < 4; rn++) {
            int n = n0 + ty * 4 + rn;
            float4 o4;
            if (z == 0) {
                o4.x = acc[rn][0] + u.sc.Sks[tx * 4 + 0];
                o4.y = acc[rn][1] + u.sc.Sks[tx * 4 + 1];
                o4.z = acc[rn][2] + u.sc.Sks[tx * 4 + 2];
                o4.w = acc[rn][3] + u.sc.Sks[tx * 4 + 3];
            } else {
                o4.x = acc[rn][0]; o4.y = acc[rn][1];
                o4.z = acc[rn][2]; o4.w = acc[rn][3];
            }
            *(float4*)&dst[n * NN + m0 + tx * 4] = o4;
        }
    }
    gsync();

    // ===== S4: softmax over (score + sp1), float4, 4 rows/block 2 warps/row =====
    if (vb < 192) {
        int wid = tid >> 5, lane = tid & 31;
        int r4 = wid >> 1, hf = wid & 1;
        int row = vb * 4 + r4;
        float4* p = (float4*)(out_score + row * NN + hf * 384);
        const float4* p1 = (const float4*)(g_sp1 + row * NN + hf * 384);
        float4 v[3];
        float mx = -1e30f;
        #pragma unroll
        for (int i = 0; i < 3; i++) {
            float4 a = p[lane + i * 32];
            float4 b = __ldg(p1 + lane + i * 32);
            a.x += b.x; a.y += b.y; a.z += b.z; a.w += b.w;
            v[i] = a;
            mx = fmaxf(mx, fmaxf(fmaxf(a.x, a.y), fmaxf(a.z, a.w)));
        }
        mx = wmax(mx);
        if (lane == 0) u.sm.mred[r4][hf] = mx;
        __syncthreads();
        mx = fmaxf(u.sm.mred[r4][0], u.sm.mred[r4][1]);
        float s = 0.f;
        #pragma unroll
        for (int i = 0; i < 3; i++) {
            v[i].x = __expf(v[i].x - mx); v[i].y = __expf(v[i].y - mx);
            v[i].z = __expf(v[i].z - mx); v[i].w = __expf(v[i].w - mx);
            s += (v[i].x + v[i].y) + (v[i].z + v[i].w);
        }
        s = wsum(s);
        if (lane == 0) u.sm.sred[r4][hf] = s;
        __syncthreads();
        float inv = 1.f / (u.sm.sred[r4][0] + u.sm.sred[r4][1]);
        #pragma unroll
        for (int i = 0; i < 3; i++) {
            v[i].x *= inv; v[i].y *= inv; v[i].z *= inv; v[i].w *= inv;
            p[lane + i * 32] = v[i];
        }
    }
    gsync();

    // ===== S5: av partials (48 n-tiles x 4 k-splits) =====
    if (vb < 192) {
        int nt = vb % 48, ks = vb / 48;
        int n0 = nt * 16;
        int d0  = (tid & 31) * 2;
        int nl0 = (tid >> 5) * 2;
        float a00 = 0.f, a01 = 0.f, a10 = 0.f, a11 = 0.f;
        for (int c = 0; c < 3; c++) {
            int mb = ks * 192 + c * 64;
            for (int idx = tid; idx < 64 * 64; idx += 256)
                u.av.Vs[idx] = g_vT[(mb + (idx >> 6)) * 64 + (idx & 63)];
            for (int idx = tid; idx < 16 * 64; idx += 256)
                u.av.Ps[idx] = out_score[(n0 + (idx >> 6)) * NN + mb + (idx & 63)];
            __syncthreads();
            #pragma unroll 4
            for (int m = 0; m < 64; m++) {
                float2 vv = *(const float2*)&u.av.Vs[m * 64 + d0];
                float p0 = u.av.Ps[nl0 * 64 + m], p1 = u.av.Ps[(nl0 + 1) * 64 + m];
                a00 = fmaf(p0, vv.x, a00); a01 = fmaf(p0, vv.y, a01);
                a10 = fmaf(p1, vv.x, a10); a11 = fmaf(p1, vv.y, a11);
            }
            __syncthreads();
        }
        float* dst = g_avp + ks * (64 * NN);
        dst[d0 * NN + n0 + nl0]           = a00;
        dst[(d0 + 1) * NN + n0 + nl0]     = a01;
        dst[d0 * NN + n0 + nl0 + 1]       = a10;
        dst[(d0 + 1) * NN + n0 + nl0 + 1] = a11;
    }
    gsync();

    // ===== S6: g1 = cw1[:,:64]@desc1 + W'@(sum avp) + b'; bn1d stat partials =====
    if (vb < 96) {
        int o0 = (vb / 6) * 8, cb = vb % 6;
        int c0 = cb * 128;
        float acc[4] = {};
        fillW8(u.g.wT, cw1, 128, o0, 0);
        __syncthreads();
        gemm8p(d1, c0, u.g.wT, acc);
        __syncthreads();
        fillW8(u.g.wT, g_Wp, 64, o0, 0);
        __syncthreads();
        gemm8s4<64 * NN>(g_avp, c0, u.g.wT, acc);
        int c = tid & 127, rg = tid >> 7;
        int ob = o0 + rg * 4;
        float vals[4];
        #pragma unroll
        for (int r = 0; r < 4; r++) {
            vals[r] = acc[r] + g_bp[ob + r];
            g_g1[(ob + r) * NN + c0 + c] = vals[r];
        }
        __syncthreads();
        rowstats8w(vals, cb * 128 + o0, g_sGp, g_qGp);
    }
    gsync();

    // ===== S7: out_desc = desc1 + cw2 @ relu(norm(g1)) + cb2 =====
    if (vb < 96) {
        int o0 = (vb / 6) * 4, c0 = (vb % 6) * 128;
        if (tid < 128) {
            float s = 0.f, q2 = 0.f;
            #pragma unroll
            for (int j = 0; j < 6; j++) { s += g_sGp[j * 128 + tid]; q2 += g_qGp[j * 128 + tid]; }
            float m = s * (1.f / NN);
            float v = q2 * (1.f / NN) - m * m;
            float sc = rsqrtf(v + 1e-5f) * __ldg(cbg + tid);
            u.f.ncf[tid] = make_float2(sc, -m * sc + __ldg(cbb + tid));
        }
        float acc[2] = {};
        fillW4(u.f.wT4, cw2, 128, o0, 0);
        __syncthreads();
        gemm4n(g_g1, c0, u.f.wT4, u.f.ncf, acc);
        __syncthreads();
        fillW4(u.f.wT4, cw2, 128, o0, 64);
        __syncthreads();
        gemm4n(g_g1 + 64 * NN, c0, u.f.wT4, u.f.ncf + 64, acc);
        int c = tid & 127, rg = tid >> 7;
        int ob = o0 + rg * 2;
        #pragma unroll
        for (int r = 0; r < 2; r++)
            out_desc[(ob + r) * NN + c0 + c] =
                acc[r] + __ldg(cb2 + ob + r) + __ldg(d1 + (ob + r) * NN + c0 + c);
    }
}

// ---------------- launch ----------------
extern "C" void kernel_launch(void* const* d_in, const int* in_sizes, int n_in,
                              void* d_out, int out_size)
{
    const float* desc1 = (const float*)d_in[0];
    const float* desc2 = (const float*)d_in[1];
    const float* qw  = (const float*)d_in[2];  const float* qb  = (const float*)d_in[3];
    const float* kw  = (const float*)d_in[4];  const float* kb  = (const float*)d_in[5];
    const float* vw  = (const float*)d_in[6];  const float* vb  = (const float*)d_in[7];
    const float* mhw = (const float*)d_in[8];  const float* mhb = (const float*)d_in[9];
    const float* cw1 = (const float*)d_in[10]; const float* cb1 = (const float*)d_in[11];
    const float* cbg = (const float*)d_in[12]; const float* cbb = (const float*)d_in[13];
    const float* cw2 = (const float*)d_in[14]; const float* cb2 = (const float*)d_in[15];
    const float* shw = (const float*)d_in[16];
    const float* bn1g = (const float*)d_in[18]; const float* bn1b = (const float*)d_in[19];
    const float* sw1 = (const float*)d_in[20]; const float* sb1 = (const float*)d_in[21];
    const float* bn2g = (const float*)d_in[22]; const float* bn2b = (const float*)d_in[23];
    const float* sw2 = (const float*)d_in[24];

    float* out = (float*)d_out;
    float* out_desc  = out;
    float* out_score = out + 64 * NN;

    k_fused<<<GB, 256>>>(desc1, desc2, qw, qb, kw, kb, vw, vb, mhw, mhb,
                         cw1, cb1, cbg, cbb, cw2, cb2, shw,
                         bn1g, bn1b, sw1, sb1, bn2g, bn2b, sw2,
                         out_desc, out_score);
}

// round 16
// speedup vs baseline: 1.2417x; 1.0960x over previous
#include <cuda_runtime.h>
#include <math.h>

#define NN 768
#define GB 288

// ---------------- scratch ----------------
__device__ float g_q[64*NN], g_k[64*NN], g_vT[NN*64];
__device__ float g_A[128*NN], g_B[128*NN];
__device__ float g_avp[6*64*NN], g_g1[128*NN];
__device__ float g_Wp[128*64], g_bp[128];
__device__ float g_sp1[NN*NN];
__device__ float g_s1p[6*128], g_q1p[6*128];
__device__ float g_sAp[6*128], g_qAp[6*128], g_sBp[6*128], g_qBp[6*128];
__device__ float g_sGp[6*128], g_qGp[6*128];
__device__ float g_Skp[16*NN];
__device__ int g_bar_count;
__device__ volatile int g_bar_gen;

// ---------------- grid barrier ----------------
__device__ __forceinline__ void gsync() {
    __threadfence();
    __syncthreads();
    if (threadIdx.x == 0) {
        int gen = g_bar_gen;
        if (atomicAdd(&g_bar_count, 1) == GB - 1) {
            g_bar_count = 0;
            __threadfence();
            g_bar_gen = gen + 1;
        } else {
            while (g_bar_gen == gen) __nanosleep(64);
        }
    }
    __syncthreads();
}

// ---------------- helpers ----------------
__device__ __forceinline__ float wsum(float v) {
    #pragma unroll
    for (int o = 16; o; o >>= 1) v += __shfl_xor_sync(0xffffffffu, v, o);
    return v;
}
__device__ __forceinline__ float wmax(float v) {
    #pragma unroll
    for (int o = 16; o; o >>= 1) v = fmaxf(v, __shfl_xor_sync(0xffffffffu, v, o));
    return v;
}

__device__ __forceinline__ void fillW8(float* wT, const float* __restrict__ W,
                                       int ldw, int o0, int koff) {
    #pragma unroll
    for (int v = threadIdx.x; v < 512; v += 256) {
        int i = v >> 3, r = v & 7;
        wT[v] = W[(o0 + r) * ldw + koff + i];
    }
}
__device__ __forceinline__ void fillW4(float* wT, const float* __restrict__ W,
                                       int ldw, int o0, int koff) {
    if (threadIdx.x < 256) {
        int i = threadIdx.x >> 2, r = threadIdx.x & 3;
        wT[threadIdx.x] = W[(o0 + r) * ldw + koff + i];
    }
}

// 4 rows x 128 cols, K=64, X streamed. acc[2] (2 row-groups of 2 rows).
__device__ __forceinline__ void gemm4p(const float* __restrict__ X, int c0,
                                       const float* wT4, float acc[2]) {
    int c = threadIdx.x & 127, rg = threadIdx.x >> 7;
    const float* xp = X + c0 + c;
    const float* wp = wT4 + rg * 2;
    #pragma unroll 8
    for (int i = 0; i < 64; i++) {
        float x = __ldg(xp + i * NN);
        float2 w = *(const float2*)(wp + i * 4);
        acc[0] = fmaf(w.x, x, acc[0]); acc[1] = fmaf(w.y, x, acc[1]);
    }
}
// 4 rows, X = sum of 6 split-k partials at stride S.
template<int S>
__device__ __forceinline__ void gemm4s6(const float* __restrict__ X, int c0,
                                        const float* wT4, float acc[2]) {
    int c = threadIdx.x & 127, rg = threadIdx.x >> 7;
    const float* xp = X + c0 + c;
    const float* wp = wT4 + rg * 2;
    #pragma unroll 4
    for (int i = 0; i < 64; i++) {
        float x = ((__ldg(xp + i * NN) + __ldg(xp + i * NN + S)) +
                   (__ldg(xp + i * NN + 2 * S) + __ldg(xp + i * NN + 3 * S))) +
                  (__ldg(xp + i * NN + 4 * S) + __ldg(xp + i * NN + 5 * S));
        float2 w = *(const float2*)(wp + i * 4);
        acc[0] = fmaf(w.x, x, acc[0]); acc[1] = fmaf(w.y, x, acc[1]);
    }
}
// 8 rows x 128 cols with norm-on-load (for S2). acc[4].
__device__ __forceinline__ void gemm8n(const float* __restrict__ X, int c0,
                                       const float* wT, const float2* nb, float acc[4]) {
    int c = threadIdx.x & 127, rg = threadIdx.x >> 7;
    const float* xp = X + c0 + c;
    const float* wp = wT + rg * 4;
    #pragma unroll 8
    for (int i = 0; i < 64; i++) {
        float2 sb = nb[i];
        float x = fmaxf(fmaf(sb.x, __ldg(xp + i * NN), sb.y), 0.f);
        float4 w = *(const float4*)(wp + i * 8);
        acc[0] = fmaf(w.x, x, acc[0]); acc[1] = fmaf(w.y, x, acc[1]);
        acc[2] = fmaf(w.z, x, acc[2]); acc[3] = fmaf(w.w, x, acc[3]);
    }
}
// 4 rows x 128 cols, K=64, norm-on-load (for S7). acc[2].
__device__ __forceinline__ void gemm4n(const float* __restrict__ X, int c0,
                                       const float* wT4, const float2* nb, float acc[2]) {
    int c = threadIdx.x & 127, rg = threadIdx.x >> 7;
    const float* xp = X + c0 + c;
    const float* wp = wT4 + rg * 2;
    #pragma unroll 8
    for (int i = 0; i < 64; i++) {
        float2 sb = nb[i];
        float x = fmaxf(fmaf(sb.x, __ldg(xp + i * NN), sb.y), 0.f);
        float2 w = *(const float2*)(wp + i * 4);
        acc[0] = fmaf(w.x, x, acc[0]); acc[1] = fmaf(w.y, x, acc[1]);
    }
}

// 8-row stats (S2). vals[4], rg in {0,1}.
__device__ __forceinline__ void rowstats8w(const float vals[4], int base,
                                           float* sdst, float* qdst) {
    __shared__ float rs[8][4], rq[8][4];
    int wid = threadIdx.x >> 5, lane = threadIdx.x & 31, rg = threadIdx.x >> 7;
    #pragma unroll
    for (int r = 0; r < 4; r++) {
        float s = wsum(vals[r]);
        float s2 = wsum(vals[r] * vals[r]);
        if (lane == 0) { rs[rg * 4 + r][wid & 3] = s; rq[rg * 4 + r][wid & 3] = s2; }
    }
    __syncthreads();
    if (threadIdx.x < 8) {
        sdst[base + threadIdx.x] = rs[threadIdx.x][0] + rs[threadIdx.x][1] +
                                   rs[threadIdx.x][2] + rs[threadIdx.x][3];
        qdst[base + threadIdx.x] = rq[threadIdx.x][0] + rq[threadIdx.x][1] +
                                   rq[threadIdx.x][2] + rq[threadIdx.x][3];
    }
}
// 4-row stats. vals[2], rows = rg*2 + r.
__device__ __forceinline__ void rowstats4w(const float vals[2], int base,
                                           float* sdst, float* qdst) {
    __shared__ float rs4[4][4], rq4[4][4];
    int wid = threadIdx.x >> 5, lane = threadIdx.x & 31, rg = threadIdx.x >> 7;
    #pragma unroll
    for (int r = 0; r < 2; r++) {
        float s = wsum(vals[r]);
        float s2 = wsum(vals[r] * vals[r]);
        if (lane == 0) { rs4[rg * 2 + r][wid & 3] = s; rq4[rg * 2 + r][wid & 3] = s2; }
    }
    __syncthreads();
    if (threadIdx.x < 4) {
        sdst[base + threadIdx.x] = rs4[threadIdx.x][0] + rs4[threadIdx.x][1] +
                                   rs4[threadIdx.x][2] + rs4[threadIdx.x][3];
        qdst[base + threadIdx.x] = rq4[threadIdx.x][0] + rq4[threadIdx.x][1] +
                                   rq4[threadIdx.x][2] + rq4[threadIdx.x][3];
    }
}

// ---------------- fused persistent kernel ----------------
__global__ void __launch_bounds__(256, 2)
k_fused(const float* __restrict__ d1, const float* __restrict__ d2,
        const float* __restrict__ qw, const float* __restrict__ qb,
        const float* __restrict__ kw, const float* __restrict__ kb,
        const float* __restrict__ vw, const float* __restrict__ vbias,
        const float* __restrict__ mhw, const float* __restrict__ mhb,
        const float* __restrict__ cw1, const float* __restrict__ cb1,
        const float* __restrict__ cbg, const float* __restrict__ cbb,
        const float* __restrict__ cw2, const float* __restrict__ cb2,
        const float* __restrict__ shw,
        const float* __restrict__ bn1g, const float* __restrict__ bn1b,
        const float* __restrict__ sw1, const float* __restrict__ sb1,
        const float* __restrict__ bn2g, const float* __restrict__ bn2b,
        const float* __restrict__ sw2,
        float* __restrict__ out_desc, float* __restrict__ out_score)
{
    __shared__ union {
        struct { float wT[512]; float2 nb[64]; float skred[128]; } g;
        struct { float As[2048]; float Bs[2048]; float w2s[64]; float Sks[64];
                 float2 scb[64]; } sc;
        struct { float mred[4][2]; float sred[4][2]; } sm;
        struct { float Vs[4096]; float Ps[1024]; } av;
        struct { float wT4[256]; float2 ncf[128]; } f;
    } u;

    int vb = blockIdx.x, tid = threadIdx.x;

    // ===== S1: qkv convs, 4-row x 128-col tiles, 288 blocks =====
    {
        int grp = vb / 96, lb = vb % 96;
        int rp = lb / 6, cb = lb % 6;          // 16 rowblocks of 4, 6 colblocks
        int o0 = rp * 4, c0 = cb * 128;
        const float *W, *X, *Bb;
        if (grp == 0)      { W = qw; X = d1; Bb = qb; }
        else if (grp == 1) { W = kw; X = d2; Bb = kb; }
        else               { W = vw; X = d2; Bb = vbias; }
        fillW4(u.g.wT, W, 64, o0, 0);
        __syncthreads();
        float acc[2] = {};
        gemm4p(X, c0, u.g.wT, acc);
        int c = tid & 127, rg = tid >> 7;
        int ob = o0 + rg * 2;
        float vals[2];
        vals[0] = acc[0] + __ldg(Bb + ob);
        vals[1] = acc[1] + __ldg(Bb + ob + 1);
        if (grp == 0) {
            g_q[ob * NN + c0 + c] = vals[0];
            g_q[(ob + 1) * NN + c0 + c] = vals[1];
            __syncthreads();
            rowstats4w(vals, cb * 128 + o0, g_s1p, g_q1p);
        } else if (grp == 1) {
            g_k[ob * NN + c0 + c] = vals[0];
            g_k[(ob + 1) * NN + c0 + c] = vals[1];
            float p = fmaf(__ldg(shw + 64 + ob), vals[0],
                           __ldg(shw + 64 + ob + 1) * vals[1]);
            if (rg == 1) u.g.skred[c] = p;
            __syncthreads();
            if (rg == 0) g_Skp[rp * NN + c0 + c] = p + u.g.skred[c];
            __syncthreads();
            rowstats4w(vals, cb * 128 + 64 + o0, g_s1p, g_q1p);
        } else {
            *(float2*)&g_vT[(c0 + c) * 64 + ob] = make_float2(vals[0], vals[1]);
        }
    }
    gsync();

    // ===== S2: A/B GEMM (192) + W' (16) + b' (1) in spare blocks =====
    if (vb < 192) {
        int half = vb / 96, lb = vb % 96;
        int o0 = (lb / 6) * 8, cb = lb % 6;
        int c0 = cb * 128;
        if (tid < 64) {
            int ch = half * 64 + tid;
            float s = 0.f, q2 = 0.f;
            #pragma unroll
            for (int j = 0; j < 6; j++) { s += g_s1p[j * 128 + ch]; q2 += g_q1p[j * 128 + ch]; }
            float m = s * (1.f / NN);
            float v = q2 * (1.f / NN) - m * m;
            float si = rsqrtf(v + 1e-3f);
            float vn = v * si * si;
            float sb = rsqrtf(vn + 1e-5f);
            float sc = si * sb * __ldg(bn1g + ch);
            u.g.nb[tid] = make_float2(sc, -m * sc + __ldg(bn1b + ch));
        }
        fillW8(u.g.wT, sw1, 128, o0, half * 64);
        __syncthreads();
        float acc[4] = {};
        gemm8n(half ? g_k : g_q, c0, u.g.wT, u.g.nb, acc);
        int c = tid & 127, rg = tid >> 7;
        int ob = o0 + rg * 4;
        float vals[4];
        if (half == 0) {
            #pragma unroll
            for (int r = 0; r < 4; r++) {
                vals[r] = acc[r];
                g_A[(ob + r) * NN + c0 + c] = vals[r];
            }
        } else {
            #pragma unroll
            for (int r = 0; r < 4; r++) {
                vals[r] = acc[r] + __ldg(sb1 + ob + r);
                g_B[(ob + r) * NN + c0 + c] = vals[r];
            }
        }
        __syncthreads();
        rowstats8w(vals, cb * 128 + o0, half ? g_sBp : g_sAp, half ? g_qBp : g_qAp);
    } else if (vb < 208) {
        int r0 = (vb - 192) * 8;
        int d = tid & 63, rg = tid >> 6;
        int row = r0 + rg * 2;
        float a0 = 0.f, a1 = 0.f;
        #pragma unroll 8
        for (int i = 0; i < 64; i++) {
            float x = __ldg(mhw + i * 64 + d);
            a0 = fmaf(__ldg(cw1 + row * 128 + 64 + i), x, a0);
            a1 = fmaf(__ldg(cw1 + (row + 1) * 128 + 64 + i), x, a1);
        }
        g_Wp[row * 64 + d] = a0;
        g_Wp[(row + 1) * 64 + d] = a1;
    } else if (vb == 208) {
        if (tid < 128) {
            float s = __ldg(cb1 + tid);
            #pragma unroll 8
            for (int i = 0; i < 64; i++)
                s = fmaf(__ldg(cw1 + tid * 128 + 64 + i), __ldg(mhb + i), s);
            g_bp[tid] = s;
        }
    }
    gsync();

    // ===== S3: score_pre partials, 64x64 tiles, o-split (288 tiles) =====
    {
        int z = vb / 144, rem = vb % 144;
        int n0 = (rem / 12) * 64, m0 = (rem % 12) * 64;
        if (tid < 64) {
            int ch = z * 64 + tid;
            float sA = 0.f, qA = 0.f, sB = 0.f, qB = 0.f;
            #pragma unroll
            for (int j = 0; j < 6; j++) {
                sA += g_sAp[j * 128 + ch]; qA += g_qAp[j * 128 + ch];
                sB += g_sBp[j * 128 + ch]; qB += g_qBp[j * 128 + ch];
            }
            float mA = sA * (1.f / NN), mB = sB * (1.f / NN);
            float vA = qA * (1.f / NN) - mA * mA;
            float vB = qB * (1.f / NN) - mB * mB;
            float m2 = mA + mB, v2 = vA + vB;
            float si = rsqrtf(v2 + 1e-3f);
            float vn = v2 * si * si;
            float sb = rsqrtf(vn + 1e-5f);
            float sc = si * sb * __ldg(bn2g + ch);
            u.sc.scb[tid] = make_float2(sc, -m2 * sc + __ldg(bn2b + ch));
            u.sc.w2s[tid] = __ldg(sw2 + ch);
        } else if (tid < 128) {
            int mm = tid - 64;
            float s = 0.f;
            #pragma unroll
            for (int rp = 0; rp < 16; rp++) s += g_Skp[rp * NN + m0 + mm];
            u.sc.Sks[mm] = s;
        }
        __syncthreads();

        int tx = tid & 15, ty = tid >> 4;
        float acc[4][4] = {};
        #pragma unroll
        for (int chk = 0; chk < 2; chk++) {
            #pragma unroll
            for (int v = tid; v < 512; v += 256) {
                int o = v >> 4, j4 = (v & 15) << 2;
                int ol = chk * 32 + o;
                int og = z * 64 + ol;
                float2 sb = u.sc.scb[ol];
                float4 a = *(const float4*)&g_A[og * NN + n0 + j4];
                a.x = fmaf(sb.x, a.x, sb.y); a.y = fmaf(sb.x, a.y, sb.y);
                a.z = fmaf(sb.x, a.z, sb.y); a.w = fmaf(sb.x, a.w, sb.y);
                *(float4*)&u.sc.As[o * 64 + j4] = a;
                float4 bv = *(const float4*)&g_B[og * NN + m0 + j4];
                bv.x *= sb.x; bv.y *= sb.x; bv.z *= sb.x; bv.w *= sb.x;
                *(float4*)&u.sc.Bs[o * 64 + j4] = bv;
            }
            __syncthreads();
            #pragma unroll 2
            for (int o = 0; o < 32; o++) {
                float4 a = *(const float4*)&u.sc.As[o * 64 + ty * 4];
                float4 bv = *(const float4*)&u.sc.Bs[o * 64 + tx * 4];
                float w = u.sc.w2s[chk * 32 + o];
                #pragma unroll
                for (int rn = 0; rn < 4; rn++) {
                    float av = (rn == 0) ? a.x : (rn == 1) ? a.y : (rn == 2) ? a.z : a.w;
                    acc[rn][0] = fmaf(w, fmaxf(av + bv.x, 0.f), acc[rn][0]);
                    acc[rn][1] = fmaf(w, fmaxf(av + bv.y, 0.f), acc[rn][1]);
                    acc[rn][2] = fmaf(w, fmaxf(av + bv.z, 0.f), acc[rn][2]);
                    acc[rn][3] = fmaf(w, fmaxf(av + bv.w, 0.f), acc[rn][3]);
                }
            }
            __syncthreads();
        }
        float* dst = z ? g_sp1 : out_score;
        #pragma unroll
        for (int rn = 0; rn < 4; rn++) {
            int n = n0 + ty * 4 + rn;
            float4 o4;
            if (z == 0) {
                o4.x = acc[rn][0] + u.sc.Sks[tx * 4 + 0];
                o4.y = acc[rn][1] + u.sc.Sks[tx * 4 + 1];
                o4.z = acc[rn][2] + u.sc.Sks[tx * 4 + 2];
                o4.w = acc[rn][3] + u.sc.Sks[tx * 4 + 3];
            } else {
                o4.x = acc[rn][0]; o4.y = acc[rn][1];
                o4.z = acc[rn][2]; o4.w = acc[rn][3];
            }
            *(float4*)&dst[n * NN + m0 + tx * 4] = o4;
        }
    }
    gsync();

    // ===== S4: softmax over (score + sp1), float4 =====
    if (vb < 192) {
        int wid = tid >> 5, lane = tid & 31;
        int r4 = wid >> 1, hf = wid & 1;
        int row = vb * 4 + r4;
        float4* p = (float4*)(out_score + row * NN + hf * 384);
        const float4* p1 = (const float4*)(g_sp1 + row * NN + hf * 384);
        float4 v[3];
        float mx = -1e30f;
        #pragma unroll
        for (int i = 0; i < 3; i++) {
            float4 a = p[lane + i * 32];
            float4 b = __ldg(p1 + lane + i * 32);
            a.x += b.x; a.y += b.y; a.z += b.z; a.w += b.w;
            v[i] = a;
            mx = fmaxf(mx, fmaxf(fmaxf(a.x, a.y), fmaxf(a.z, a.w)));
        }
        mx = wmax(mx);
        if (lane == 0) u.sm.mred[r4][hf] = mx;
        __syncthreads();
        mx = fmaxf(u.sm.mred[r4][0], u.sm.mred[r4][1]);
        float s = 0.f;
        #pragma unroll
        for (int i = 0; i < 3; i++) {
            v[i].x = __expf(v[i].x - mx); v[i].y = __expf(v[i].y - mx);
            v[i].z = __expf(v[i].z - mx); v[i].w = __expf(v[i].w - mx);
            s += (v[i].x + v[i].y) + (v[i].z + v[i].w);
        }
        s = wsum(s);
        if (lane == 0) u.sm.sred[r4][hf] = s;
        __syncthreads();
        float inv = 1.f / (u.sm.sred[r4][0] + u.sm.sred[r4][1]);
        #pragma unroll
        for (int i = 0; i < 3; i++) {
            v[i].x *= inv; v[i].y *= inv; v[i].z *= inv; v[i].w *= inv;
            p[lane + i * 32] = v[i];
        }
    }
    gsync();

    // ===== S5: av partials (48 n-tiles x 6 k-splits = 288 blocks) =====
    {
        int nt = vb % 48, ks = vb / 48;
        int n0 = nt * 16;
        int d0  = (tid & 31) * 2;
        int nl0 = (tid >> 5) * 2;
        float a00 = 0.f, a01 = 0.f, a10 = 0.f, a11 = 0.f;
        for (int c = 0; c < 2; c++) {
            int mb = ks * 128 + c * 64;
            for (int idx = tid; idx < 64 * 64; idx += 256)
                u.av.Vs[idx] = g_vT[(mb + (idx >> 6)) * 64 + (idx & 63)];
            for (int idx = tid; idx < 16 * 64; idx += 256)
                u.av.Ps[idx] = out_score[(n0 + (idx >> 6)) * NN + mb + (idx & 63)];
            __syncthreads();
            #pragma unroll 4
            for (int m = 0; m < 64; m++) {
                float2 vv = *(const float2*)&u.av.Vs[m * 64 + d0];
                float p0 = u.av.Ps[nl0 * 64 + m], p1 = u.av.Ps[(nl0 + 1) * 64 + m];
                a00 = fmaf(p0, vv.x, a00); a01 = fmaf(p0, vv.y, a01);
                a10 = fmaf(p1, vv.x, a10); a11 = fmaf(p1, vv.y, a11);
            }
            __syncthreads();
        }
        float* dst = g_avp + ks * (64 * NN);
        dst[d0 * NN + n0 + nl0]           = a00;
        dst[(d0 + 1) * NN + n0 + nl0]     = a01;
        dst[d0 * NN + n0 + nl0 + 1]       = a10;
        dst[(d0 + 1) * NN + n0 + nl0 + 1] = a11;
    }
    gsync();

    // ===== S6: g1 = cw1[:,:64]@desc1 + W'@(sum 6 avp) + b'; 4-row tiles, 192 blocks =====
    if (vb < 192) {
        int o0 = (vb / 6) * 4, cb = vb % 6;
        int c0 = cb * 128;
        float acc[2] = {};
        fillW4(u.g.wT, cw1, 128, o0, 0);
        __syncthreads();
        gemm4p(d1, c0, u.g.wT, acc);
        __syncthreads();
        fillW4(u.g.wT, g_Wp, 64, o0, 0);
        __syncthreads();
        gemm4s6<64 * NN>(g_avp, c0, u.g.wT, acc);
        int c = tid & 127, rg = tid >> 7;
        int ob = o0 + rg * 2;
        float vals[2];
        vals[0] = acc[0] + g_bp[ob];
        vals[1] = acc[1] + g_bp[ob + 1];
        g_g1[ob * NN + c0 + c] = vals[0];
        g_g1[(ob + 1) * NN + c0 + c] = vals[1];
        __syncthreads();
        rowstats4w(vals, cb * 128 + o0, g_sGp, g_qGp);
    }
    gsync();

    // ===== S7: out_desc = desc1 + cw2 @ relu(norm(g1)) + cb2; 96 blocks =====
    if (vb < 96) {
        int o0 = (vb / 6) * 4, c0 = (vb % 6) * 128;
        if (tid < 128) {
            float s = 0.f, q2 = 0.f;
            #pragma unroll
            for (int j = 0; j < 6; j++) { s += g_sGp[j * 128 + tid]; q2 += g_qGp[j * 128 + tid]; }
            float m = s * (1.f / NN);
            float v = q2 * (1.f / NN) - m * m;
            float sc = rsqrtf(v + 1e-5f) * __ldg(cbg + tid);
            u.f.ncf[tid] = make_float2(sc, -m * sc + __ldg(cbb + tid));
        }
        float acc[2] = {};
        fillW4(u.f.wT4, cw2, 128, o0, 0);
        __syncthreads();
        gemm4n(g_g1, c0, u.f.wT4, u.f.ncf, acc);
        __syncthreads();
        fillW4(u.f.wT4, cw2, 128, o0, 64);
        __syncthreads();
        gemm4n(g_g1 + 64 * NN, c0, u.f.wT4, u.f.ncf + 64, acc);
        int c = tid & 127, rg = tid >> 7;
        int ob = o0 + rg * 2;
        #pragma unroll
        for (int r = 0; r < 2; r++)
            out_desc[(ob + r) * NN + c0 + c] =
                acc[r] + __ldg(cb2 + ob + r) + __ldg(d1 + (ob + r) * NN + c0 + c);
    }
}

// ---------------- launch ----------------
extern "C" void kernel_launch(void* const* d_in, const int* in_sizes, int n_in,
                              void* d_out, int out_size)
{
    const float* desc1 = (const float*)d_in[0];
    const float* desc2 = (const float*)d_in[1];
    const float* qw  = (const float*)d_in[2];  const float* qb  = (const float*)d_in[3];
    const float* kw  = (const float*)d_in[4];  const float* kb  = (const float*)d_in[5];
    const float* vw  = (const float*)d_in[6];  const float* vb  = (const float*)d_in[7];
    const float* mhw = (const float*)d_in[8];  const float* mhb = (const float*)d_in[9];
    const float* cw1 = (const float*)d_in[10]; const float* cb1 = (const float*)d_in[11];
    const float* cbg = (const float*)d_in[12]; const float* cbb = (const float*)d_in[13];
    const float* cw2 = (const float*)d_in[14]; const float* cb2 = (const float*)d_in[15];
    const float* shw = (const float*)d_in[16];
    const float* bn1g = (const float*)d_in[18]; const float* bn1b = (const float*)d_in[19];
    const float* sw1 = (const float*)d_in[20]; const float* sb1 = (const float*)d_in[21];
    const float* bn2g = (const float*)d_in[22]; const float* bn2b = (const float*)d_in[23];
    const float* sw2 = (const float*)d_in[24];

    float* out = (float*)d_out;
    float* out_desc  = out;
    float* out_score = out + 64 * NN;

    k_fused<<<GB, 256>>>(desc1, desc2, qw, qb, kw, kb, vw, vb, mhw, mhb,
                         cw1, cb1, cbg, cbb, cw2, cb2, shw,
                         bn1g, bn1b, sw1, sb1, bn2g, bn2b, sw2,
                         out_desc, out_score);
}